// round 1
// baseline (speedup 1.0000x reference)
#include <cuda_runtime.h>
#include <cuda_bf16.h>
#include <cstdint>
#include <cmath>

// Problem constants
#define BATCH 64
#define TSTEPS 512
#define DIM 1024
#define OUTD 1024
#define M_TOTAL (BATCH * TSTEPS)   // 32768
#define NCHUNKS 8                  // N / BN

// Scratch (device globals: no allocations allowed)
__device__ float g_WaS[BATCH * OUTD];            // prev@Wa + Ba
__device__ float g_partial[M_TOTAL * NCHUNKS];   // per-(row, n-chunk) partial Va-dot
__device__ float g_sm[BATCH * TSTEPS];           // softmax weights

// ---------------------------------------------------------------------------
// Kernel 1: WaS[b,o] = Ba[o] + sum_k prev[b,k] * Wa[k,o]
// grid 128 blocks (o-chunks of 8), 256 threads
// ---------------------------------------------------------------------------
__global__ __launch_bounds__(256) void was_kernel(
    const float* __restrict__ prev, const float* __restrict__ Wa,
    const float* __restrict__ Ba)
{
    int o0 = blockIdx.x * 8;
    int oo = threadIdx.x & 7;
    int bq = threadIdx.x >> 3;   // 0..31, each handles 2 batch rows

    __shared__ float ps[64][33];
    __shared__ float ws[32][9];

    float acc0 = 0.f, acc1 = 0.f;
    for (int k0 = 0; k0 < OUTD; k0 += 32) {
        #pragma unroll
        for (int j = 0; j < 8; ++j) {
            int e = threadIdx.x + j * 256;   // 0..2047
            int bb = e >> 5, kk = e & 31;
            ps[bb][kk] = prev[bb * OUTD + k0 + kk];
        }
        {
            int kk = threadIdx.x >> 3, o = threadIdx.x & 7;
            ws[kk][o] = Wa[(size_t)(k0 + kk) * OUTD + o0 + o];
        }
        __syncthreads();
        #pragma unroll
        for (int kk = 0; kk < 32; ++kk) {
            float w = ws[kk][oo];
            acc0 = fmaf(ps[bq * 2 + 0][kk], w, acc0);
            acc1 = fmaf(ps[bq * 2 + 1][kk], w, acc1);
        }
        __syncthreads();
    }
    float bav = Ba[o0 + oo];
    g_WaS[(bq * 2 + 0) * OUTD + o0 + oo] = acc0 + bav;
    g_WaS[(bq * 2 + 1) * OUTD + o0 + oo] = acc1 + bav;
}

// ---------------------------------------------------------------------------
// Kernel 2: fused GEMM  C = inputs @ Ua  (M=32768, N=1024, K=1024, tf32 MMA)
// epilogue: partial[m, nchunk] = sum_n Va[n] * tanh(C[m,n] + WaS[b,n])
// BM=128, BN=128, BK=16, 256 threads, 8 warps (4M x 2N), warp tile 32x64
// ---------------------------------------------------------------------------
#define BM 128
#define BN 128
#define BK 16
#define NKT (DIM / BK)   // 64

__device__ __forceinline__ uint32_t f2tf32(float x) {
    uint32_t y;
    asm("cvt.rna.tf32.f32 %0, %1;" : "=r"(y) : "f"(x));
    return y;
}

__device__ __forceinline__ void mma_tf32(float* c, const uint32_t* a, const uint32_t* b) {
    asm("mma.sync.aligned.m16n8k8.row.col.f32.tf32.tf32.f32 "
        "{%0,%1,%2,%3}, {%4,%5,%6,%7}, {%8,%9}, {%0,%1,%2,%3};"
        : "+f"(c[0]), "+f"(c[1]), "+f"(c[2]), "+f"(c[3])
        : "r"(a[0]), "r"(a[1]), "r"(a[2]), "r"(a[3]), "r"(b[0]), "r"(b[1]));
}

__global__ __launch_bounds__(256) void attn_gemm_kernel(
    const float* __restrict__ X,   // [M_TOTAL, DIM]
    const float* __restrict__ Ua,  // [DIM, OUTD]
    const float* __restrict__ Va)  // [OUTD]
{
    __shared__ uint32_t As[2][BM][20];    // padded: conflict-free A-frag loads
    __shared__ uint32_t Bs[2][BK][132];
    __shared__ float sc[2][BM];
    __shared__ float vva[BN];
    __shared__ float wss[BN];

    const int tid = threadIdx.x;
    const int lane = tid & 31;
    const int wid = tid >> 5;
    const int wm = wid & 3;        // warp M index (0..3)
    const int wn = wid >> 2;       // warp N index (0..1)
    const int n0 = blockIdx.x * BN;
    const int m0 = blockIdx.y * BM;
    const int b  = m0 >> 9;        // batch index (128 rows always within one b)

    // gmem load mapping
    const int arow = tid >> 2;            // 0..63 (+64 for second half)
    const int acol = (tid & 3) << 2;      // 0,4,8,12
    const int brow = tid >> 5;            // 0..7 (+8)
    const int bcol = (tid & 31) << 2;     // 0..124

    const float* Ap0 = X + (size_t)(m0 + arow) * DIM + acol;
    const float* Ap1 = X + (size_t)(m0 + arow + 64) * DIM + acol;
    const float* Bp0 = Ua + (size_t)brow * OUTD + n0 + bcol;
    const float* Bp1 = Ua + (size_t)(brow + 8) * OUTD + n0 + bcol;

    float acc[2][8][4];
    #pragma unroll
    for (int mi = 0; mi < 2; ++mi)
        #pragma unroll
        for (int ni = 0; ni < 8; ++ni)
            #pragma unroll
            for (int j = 0; j < 4; ++j) acc[mi][ni][j] = 0.f;

    // preload tile 0 into smem buffer 0
    {
        float4 a0 = *reinterpret_cast<const float4*>(Ap0);
        float4 a1 = *reinterpret_cast<const float4*>(Ap1);
        float4 q0 = *reinterpret_cast<const float4*>(Bp0);
        float4 q1 = *reinterpret_cast<const float4*>(Bp1);
        uint4 u;
        u.x = f2tf32(a0.x); u.y = f2tf32(a0.y); u.z = f2tf32(a0.z); u.w = f2tf32(a0.w);
        *reinterpret_cast<uint4*>(&As[0][arow][acol]) = u;
        u.x = f2tf32(a1.x); u.y = f2tf32(a1.y); u.z = f2tf32(a1.z); u.w = f2tf32(a1.w);
        *reinterpret_cast<uint4*>(&As[0][arow + 64][acol]) = u;
        u.x = f2tf32(q0.x); u.y = f2tf32(q0.y); u.z = f2tf32(q0.z); u.w = f2tf32(q0.w);
        *reinterpret_cast<uint4*>(&Bs[0][brow][bcol]) = u;
        u.x = f2tf32(q1.x); u.y = f2tf32(q1.y); u.z = f2tf32(q1.z); u.w = f2tf32(q1.w);
        *reinterpret_cast<uint4*>(&Bs[0][brow + 8][bcol]) = u;
    }
    __syncthreads();

    for (int kt = 0; kt < NKT; ++kt) {
        const int buf = kt & 1;
        float4 na0, na1, nb0, nb1;
        if (kt < NKT - 1) {
            int koff = (kt + 1) * BK;
            na0 = *reinterpret_cast<const float4*>(Ap0 + koff);
            na1 = *reinterpret_cast<const float4*>(Ap1 + koff);
            nb0 = *reinterpret_cast<const float4*>(Bp0 + (size_t)koff * OUTD);
            nb1 = *reinterpret_cast<const float4*>(Bp1 + (size_t)koff * OUTD);
        }

        #pragma unroll
        for (int ks = 0; ks < 2; ++ks) {
            const int kb = ks * 8;
            uint32_t af[2][4];
            uint32_t bf[8][2];
            #pragma unroll
            for (int mi = 0; mi < 2; ++mi) {
                int r = wm * 32 + mi * 16 + (lane >> 2);
                int c = kb + (lane & 3);
                af[mi][0] = As[buf][r][c];
                af[mi][1] = As[buf][r + 8][c];
                af[mi][2] = As[buf][r][c + 4];
                af[mi][3] = As[buf][r + 8][c + 4];
            }
            #pragma unroll
            for (int ni = 0; ni < 8; ++ni) {
                int rr = kb + (lane & 3);
                int cc = wn * 64 + ni * 8 + (lane >> 2);
                bf[ni][0] = Bs[buf][rr][cc];
                bf[ni][1] = Bs[buf][rr + 4][cc];
            }
            #pragma unroll
            for (int mi = 0; mi < 2; ++mi)
                #pragma unroll
                for (int ni = 0; ni < 8; ++ni)
                    mma_tf32(acc[mi][ni], af[mi], bf[ni]);
        }

        if (kt < NKT - 1) {
            const int nbuf = buf ^ 1;
            uint4 u;
            u.x = f2tf32(na0.x); u.y = f2tf32(na0.y); u.z = f2tf32(na0.z); u.w = f2tf32(na0.w);
            *reinterpret_cast<uint4*>(&As[nbuf][arow][acol]) = u;
            u.x = f2tf32(na1.x); u.y = f2tf32(na1.y); u.z = f2tf32(na1.z); u.w = f2tf32(na1.w);
            *reinterpret_cast<uint4*>(&As[nbuf][arow + 64][acol]) = u;
            u.x = f2tf32(nb0.x); u.y = f2tf32(nb0.y); u.z = f2tf32(nb0.z); u.w = f2tf32(nb0.w);
            *reinterpret_cast<uint4*>(&Bs[nbuf][brow][bcol]) = u;
            u.x = f2tf32(nb1.x); u.y = f2tf32(nb1.y); u.z = f2tf32(nb1.z); u.w = f2tf32(nb1.w);
            *reinterpret_cast<uint4*>(&Bs[nbuf][brow + 8][bcol]) = u;
        }
        __syncthreads();
    }

    // Stage Va and WaS rows for this n-chunk
    if (tid < BN) {
        vva[tid] = Va[n0 + tid];
        wss[tid] = g_WaS[b * OUTD + n0 + tid];
    }
    __syncthreads();

    // Epilogue: tanh + Va-dot, reduce per row
    float rowsum[2][2] = {{0.f, 0.f}, {0.f, 0.f}};
    #pragma unroll
    for (int mi = 0; mi < 2; ++mi) {
        #pragma unroll
        for (int ni = 0; ni < 8; ++ni) {
            #pragma unroll
            for (int j = 0; j < 4; ++j) {
                int nl = wn * 64 + ni * 8 + ((lane & 3) << 1) + (j & 1);
                float v = acc[mi][ni][j] + wss[nl];
                rowsum[mi][j >> 1] += tanhf(v) * vva[nl];
            }
        }
    }
    #pragma unroll
    for (int mi = 0; mi < 2; ++mi) {
        #pragma unroll
        for (int h = 0; h < 2; ++h) {
            float s = rowsum[mi][h];
            s += __shfl_xor_sync(0xffffffffu, s, 1);
            s += __shfl_xor_sync(0xffffffffu, s, 2);
            if ((lane & 3) == 0) {
                int r = wm * 32 + mi * 16 + (lane >> 2) + h * 8;
                sc[wn][r] = s;
            }
        }
    }
    __syncthreads();
    if (tid < BM) {
        g_partial[(size_t)(m0 + tid) * NCHUNKS + blockIdx.x] = sc[0][tid] + sc[1][tid];
    }
}

// ---------------------------------------------------------------------------
// Kernel 3: relu + softmax over timesteps. 64 blocks x 512 threads
// ---------------------------------------------------------------------------
__global__ __launch_bounds__(512) void softmax_kernel()
{
    int bb = blockIdx.x, t = threadIdx.x;
    const float* p = g_partial + ((size_t)bb * TSTEPS + t) * NCHUNKS;
    float s = 0.f;
    #pragma unroll
    for (int i = 0; i < NCHUNKS; ++i) s += p[i];
    s = fmaxf(s, 0.f);

    __shared__ float red[16];
    __shared__ float smax, ssum;

    float m = s;
    #pragma unroll
    for (int o = 16; o; o >>= 1) m = fmaxf(m, __shfl_xor_sync(0xffffffffu, m, o));
    if ((t & 31) == 0) red[t >> 5] = m;
    __syncthreads();
    if (t == 0) {
        float v = red[0];
        #pragma unroll
        for (int i = 1; i < 16; ++i) v = fmaxf(v, red[i]);
        smax = v;
    }
    __syncthreads();

    float e = expf(s - smax);
    float q = e;
    #pragma unroll
    for (int o = 16; o; o >>= 1) q += __shfl_xor_sync(0xffffffffu, q, o);
    if ((t & 31) == 0) red[t >> 5] = q;
    __syncthreads();
    if (t == 0) {
        float v = 0.f;
        #pragma unroll
        for (int i = 0; i < 16; ++i) v += red[i];
        ssum = v;
    }
    __syncthreads();

    g_sm[bb * TSTEPS + t] = e / ssum;
}

// ---------------------------------------------------------------------------
// Kernel 4: context[b,d] = sum_t inputs[b,t,d] * sm[b,t]. grid (64,4) x 256
// ---------------------------------------------------------------------------
__global__ __launch_bounds__(256) void context_kernel(
    const float* __restrict__ X, float* __restrict__ out)
{
    int bb = blockIdx.x;
    int d = blockIdx.y * 256 + threadIdx.x;

    __shared__ float w[TSTEPS];
    for (int i = threadIdx.x; i < TSTEPS; i += 256) w[i] = g_sm[bb * TSTEPS + i];
    __syncthreads();

    const float* xp = X + (size_t)bb * TSTEPS * DIM + d;
    float acc = 0.f;
    #pragma unroll 8
    for (int t = 0; t < TSTEPS; ++t) acc = fmaf(xp[(size_t)t * DIM], w[t], acc);
    out[bb * DIM + d] = acc;
}

// ---------------------------------------------------------------------------
extern "C" void kernel_launch(void* const* d_in, const int* in_sizes, int n_in,
                              void* d_out, int out_size)
{
    const float* inputs = (const float*)d_in[0];
    const float* prev   = (const float*)d_in[1];
    const float* Wa     = (const float*)d_in[2];
    const float* Ua     = (const float*)d_in[3];
    const float* Va     = (const float*)d_in[4];
    const float* Ba     = (const float*)d_in[5];
    float* out = (float*)d_out;

    was_kernel<<<128, 256>>>(prev, Wa, Ba);
    dim3 g2(NCHUNKS, M_TOTAL / BM);   // (8, 256)
    attn_gemm_kernel<<<g2, 256>>>(inputs, Ua, Va);
    softmax_kernel<<<BATCH, TSTEPS>>>();
    context_kernel<<<dim3(BATCH, DIM / 256), 256>>>(inputs, out);
}

// round 3
// speedup vs baseline: 2.0065x; 2.0065x over previous
#include <cuda_runtime.h>
#include <cuda_fp16.h>
#include <cstdint>
#include <cmath>

// Problem constants
#define BATCH 64
#define TSTEPS 512
#define DIM 1024
#define OUTD 1024
#define M_TOTAL (BATCH * TSTEPS)   // 32768
#define NCHUNKS 8                  // N / BN

// Scratch (device globals: no allocations allowed)
__device__ float g_WaS[BATCH * OUTD];            // prev@Wa + Ba
__device__ float g_partial[M_TOTAL * NCHUNKS];   // per-(row, n-chunk) partial Va-dot
__device__ float g_sm[BATCH * TSTEPS];           // softmax weights

// pack two fp32 -> fp16x2 (lo in lower 16 bits)
__device__ __forceinline__ uint32_t pack_f16x2(float lo, float hi) {
    uint32_t r;
    asm("cvt.rn.f16x2.f32 %0, %1, %2;" : "=r"(r) : "f"(hi), "f"(lo));
    return r;
}

__device__ __forceinline__ void mma_f16(float* c, const uint32_t* a, const uint32_t* b) {
    asm("mma.sync.aligned.m16n8k16.row.col.f32.f16.f16.f32 "
        "{%0,%1,%2,%3}, {%4,%5,%6,%7}, {%8,%9}, {%0,%1,%2,%3};"
        : "+f"(c[0]), "+f"(c[1]), "+f"(c[2]), "+f"(c[3])
        : "r"(a[0]), "r"(a[1]), "r"(a[2]), "r"(a[3]), "r"(b[0]), "r"(b[1]));
}

// ---------------------------------------------------------------------------
// Kernel 1: WaS[b,o] = Ba[o] + sum_k prev[b,k] * Wa[k,o]
// ---------------------------------------------------------------------------
__global__ __launch_bounds__(256) void was_kernel(
    const float* __restrict__ prev, const float* __restrict__ Wa,
    const float* __restrict__ Ba)
{
    int o0 = blockIdx.x * 8;
    int oo = threadIdx.x & 7;
    int bq = threadIdx.x >> 3;

    __shared__ float ps[64][33];
    __shared__ float ws[32][9];

    float acc0 = 0.f, acc1 = 0.f;
    for (int k0 = 0; k0 < OUTD; k0 += 32) {
        #pragma unroll
        for (int j = 0; j < 8; ++j) {
            int e = threadIdx.x + j * 256;
            int bb = e >> 5, kk = e & 31;
            ps[bb][kk] = prev[bb * OUTD + k0 + kk];
        }
        {
            int kk = threadIdx.x >> 3, o = threadIdx.x & 7;
            ws[kk][o] = Wa[(size_t)(k0 + kk) * OUTD + o0 + o];
        }
        __syncthreads();
        #pragma unroll
        for (int kk = 0; kk < 32; ++kk) {
            float w = ws[kk][oo];
            acc0 = fmaf(ps[bq * 2 + 0][kk], w, acc0);
            acc1 = fmaf(ps[bq * 2 + 1][kk], w, acc1);
        }
        __syncthreads();
    }
    float bav = Ba[o0 + oo];
    g_WaS[(bq * 2 + 0) * OUTD + o0 + oo] = acc0 + bav;
    g_WaS[(bq * 2 + 1) * OUTD + o0 + oo] = acc1 + bav;
}

// ---------------------------------------------------------------------------
// Kernel 2: fused GEMM  C = inputs @ Ua  (fp16 mma.sync m16n8k16, fp32 accum)
// epilogue: partial[m, nchunk] = sum_n Va[n] * tanh(C[m,n] + WaS[b,n])
// BM=128, BN=128, BK=32, 256 threads, 8 warps (4M x 2N), warp tile 32x64.
// SMEM stores (k,k+1) half-pairs packed in u32: every fragment = 1 LDS.b32.
//   As: [128][20]  pad->20: frag banks (row*20 + w) all-distinct
//   Bs: [16][136]  pad->136: frag banks (kp*136 + n) all-distinct
// ---------------------------------------------------------------------------
#define BM 128
#define BN 128
#define BK 32
#define NKT (DIM / BK)   // 32

__global__ __launch_bounds__(256, 2) void attn_gemm_kernel(
    const float* __restrict__ X,   // [M_TOTAL, DIM]
    const float* __restrict__ Ua,  // [DIM, OUTD]
    const float* __restrict__ Va)  // [OUTD]
{
    __shared__ uint32_t As[2][BM][20];    // 20480 B
    __shared__ uint32_t Bs[2][16][136];   // 17408 B
    __shared__ float sc[2][BM];
    __shared__ float vva[BN];
    __shared__ float wss[BN];

    const int tid = threadIdx.x;
    const int lane = tid & 31;
    const int wid = tid >> 5;
    const int wm = wid & 3;        // warp M index (0..3)
    const int wn = wid >> 2;       // warp N index (0..1)
    const int gid = lane >> 2;     // 0..7
    const int t4  = lane & 3;      // 0..3
    const int n0 = blockIdx.x * BN;
    const int m0 = blockIdx.y * BM;
    const int b  = m0 >> 9;

    float acc[2][8][4];
    #pragma unroll
    for (int mi = 0; mi < 2; ++mi)
        #pragma unroll
        for (int ni = 0; ni < 8; ++ni)
            #pragma unroll
            for (int j = 0; j < 4; ++j) acc[mi][ni][j] = 0.f;

    // ---- tile load helpers (A: 4 iters of float4; B: 2 iters of paired rows)
    auto load_store_tile = [&](int kt, int buf, const float4* a4,
                               const float4* be, const float4* bo) {
        #pragma unroll
        for (int i = 0; i < 4; ++i) {
            int idx = i * 256 + tid;
            int r = idx >> 3, c4 = idx & 7;
            uint32_t p0 = pack_f16x2(a4[i].x, a4[i].y);
            uint32_t p1 = pack_f16x2(a4[i].z, a4[i].w);
            As[buf][r][c4 * 2 + 0] = p0;
            As[buf][r][c4 * 2 + 1] = p1;
        }
        #pragma unroll
        for (int i = 0; i < 2; ++i) {
            int idx = i * 256 + tid;
            int p = idx >> 5, q = idx & 31;
            uint32_t w0 = pack_f16x2(be[i].x, bo[i].x);
            uint32_t w1 = pack_f16x2(be[i].y, bo[i].y);
            uint32_t w2 = pack_f16x2(be[i].z, bo[i].z);
            uint32_t w3 = pack_f16x2(be[i].w, bo[i].w);
            uint4 u = make_uint4(w0, w1, w2, w3);
            *reinterpret_cast<uint4*>(&Bs[buf][p][q * 4]) = u;
        }
    };

    // ---- preload tile 0
    {
        float4 a4[4], be[2], bo[2];
        #pragma unroll
        for (int i = 0; i < 4; ++i) {
            int idx = i * 256 + tid;
            int r = idx >> 3, c4 = idx & 7;
            a4[i] = *reinterpret_cast<const float4*>(
                X + (size_t)(m0 + r) * DIM + c4 * 4);
        }
        #pragma unroll
        for (int i = 0; i < 2; ++i) {
            int idx = i * 256 + tid;
            int p = idx >> 5, q = idx & 31;
            const float* bp = Ua + (size_t)(2 * p) * OUTD + n0 + q * 4;
            be[i] = *reinterpret_cast<const float4*>(bp);
            bo[i] = *reinterpret_cast<const float4*>(bp + OUTD);
        }
        load_store_tile(0, 0, a4, be, bo);
    }
    __syncthreads();

    for (int kt = 0; kt < NKT; ++kt) {
        const int buf = kt & 1;

        // prefetch next tile to registers
        float4 a4[4], be[2], bo[2];
        if (kt < NKT - 1) {
            int k0 = (kt + 1) * BK;
            #pragma unroll
            for (int i = 0; i < 4; ++i) {
                int idx = i * 256 + tid;
                int r = idx >> 3, c4 = idx & 7;
                a4[i] = *reinterpret_cast<const float4*>(
                    X + (size_t)(m0 + r) * DIM + k0 + c4 * 4);
            }
            #pragma unroll
            for (int i = 0; i < 2; ++i) {
                int idx = i * 256 + tid;
                int p = idx >> 5, q = idx & 31;
                const float* bp = Ua + (size_t)(k0 + 2 * p) * OUTD + n0 + q * 4;
                be[i] = *reinterpret_cast<const float4*>(bp);
                bo[i] = *reinterpret_cast<const float4*>(bp + OUTD);
            }
        }

        // compute: 2 k16 steps
        #pragma unroll
        for (int ks = 0; ks < 2; ++ks) {
            const int w0 = ks * 8 + t4;
            uint32_t af[2][4];
            uint32_t bf[8][2];
            #pragma unroll
            for (int mi = 0; mi < 2; ++mi) {
                int r = wm * 32 + mi * 16 + gid;
                af[mi][0] = As[buf][r][w0];
                af[mi][1] = As[buf][r + 8][w0];
                af[mi][2] = As[buf][r][w0 + 4];
                af[mi][3] = As[buf][r + 8][w0 + 4];
            }
            #pragma unroll
            for (int ni = 0; ni < 8; ++ni) {
                int n = wn * 64 + ni * 8 + gid;
                bf[ni][0] = Bs[buf][w0][n];
                bf[ni][1] = Bs[buf][w0 + 4][n];
            }
            #pragma unroll
            for (int mi = 0; mi < 2; ++mi)
                #pragma unroll
                for (int ni = 0; ni < 8; ++ni)
                    mma_f16(acc[mi][ni], af[mi], bf[ni]);
        }

        if (kt < NKT - 1)
            load_store_tile(kt + 1, buf ^ 1, a4, be, bo);
        __syncthreads();
    }

    // Stage Va and WaS rows for this n-chunk
    if (tid < BN) {
        vva[tid] = Va[n0 + tid];
        wss[tid] = g_WaS[b * OUTD + n0 + tid];
    }
    __syncthreads();

    // Epilogue: tanh + Va-dot, reduce per row
    float rowsum[2][2] = {{0.f, 0.f}, {0.f, 0.f}};
    #pragma unroll
    for (int mi = 0; mi < 2; ++mi) {
        #pragma unroll
        for (int ni = 0; ni < 8; ++ni) {
            #pragma unroll
            for (int j = 0; j < 4; ++j) {
                int nl = wn * 64 + ni * 8 + (t4 << 1) + (j & 1);
                float v = acc[mi][ni][j] + wss[nl];
                rowsum[mi][j >> 1] += tanhf(v) * vva[nl];
            }
        }
    }
    #pragma unroll
    for (int mi = 0; mi < 2; ++mi) {
        #pragma unroll
        for (int h = 0; h < 2; ++h) {
            float s = rowsum[mi][h];
            s += __shfl_xor_sync(0xffffffffu, s, 1);
            s += __shfl_xor_sync(0xffffffffu, s, 2);
            if (t4 == 0) {
                int r = wm * 32 + mi * 16 + gid + h * 8;
                sc[wn][r] = s;
            }
        }
    }
    __syncthreads();
    if (tid < BM) {
        g_partial[(size_t)(m0 + tid) * NCHUNKS + blockIdx.x] = sc[0][tid] + sc[1][tid];
    }
}

// ---------------------------------------------------------------------------
// Kernel 3: relu + softmax over timesteps. 64 blocks x 512 threads
// ---------------------------------------------------------------------------
__global__ __launch_bounds__(512) void softmax_kernel()
{
    int bb = blockIdx.x, t = threadIdx.x;
    const float* p = g_partial + ((size_t)bb * TSTEPS + t) * NCHUNKS;
    float s = 0.f;
    #pragma unroll
    for (int i = 0; i < NCHUNKS; ++i) s += p[i];
    s = fmaxf(s, 0.f);

    __shared__ float red[16];
    __shared__ float smax, ssum;

    float m = s;
    #pragma unroll
    for (int o = 16; o; o >>= 1) m = fmaxf(m, __shfl_xor_sync(0xffffffffu, m, o));
    if ((t & 31) == 0) red[t >> 5] = m;
    __syncthreads();
    if (t == 0) {
        float v = red[0];
        #pragma unroll
        for (int i = 1; i < 16; ++i) v = fmaxf(v, red[i]);
        smax = v;
    }
    __syncthreads();

    float e = expf(s - smax);
    float q = e;
    #pragma unroll
    for (int o = 16; o; o >>= 1) q += __shfl_xor_sync(0xffffffffu, q, o);
    if ((t & 31) == 0) red[t >> 5] = q;
    __syncthreads();
    if (t == 0) {
        float v = 0.f;
        #pragma unroll
        for (int i = 0; i < 16; ++i) v += red[i];
        ssum = v;
    }
    __syncthreads();

    g_sm[bb * TSTEPS + t] = e / ssum;
}

// ---------------------------------------------------------------------------
// Kernel 4: context[b,d] = sum_t inputs[b,t,d] * sm[b,t]
// grid (64, 16) x 256: each block does 64 d-cols with a 4-way T split
// ---------------------------------------------------------------------------
__global__ __launch_bounds__(256) void context_kernel(
    const float* __restrict__ X, float* __restrict__ out)
{
    int bb = blockIdx.x;
    int d0 = blockIdx.y * 64;
    int dd = threadIdx.x & 63;
    int tg = threadIdx.x >> 6;

    __shared__ float w[TSTEPS];
    __shared__ float part[4][64];
    for (int i = threadIdx.x; i < TSTEPS; i += 256) w[i] = g_sm[bb * TSTEPS + i];
    __syncthreads();

    const float* xp = X + (size_t)bb * TSTEPS * DIM + d0 + dd;
    float acc = 0.f;
    int tbase = tg * 128;
    #pragma unroll 8
    for (int t = 0; t < 128; ++t)
        acc = fmaf(xp[(size_t)(tbase + t) * DIM], w[tbase + t], acc);
    part[tg][dd] = acc;
    __syncthreads();
    if (threadIdx.x < 64)
        out[bb * DIM + d0 + threadIdx.x] =
            part[0][threadIdx.x] + part[1][threadIdx.x] +
            part[2][threadIdx.x] + part[3][threadIdx.x];
}

// ---------------------------------------------------------------------------
extern "C" void kernel_launch(void* const* d_in, const int* in_sizes, int n_in,
                              void* d_out, int out_size)
{
    const float* inputs = (const float*)d_in[0];
    const float* prev   = (const float*)d_in[1];
    const float* Wa     = (const float*)d_in[2];
    const float* Ua     = (const float*)d_in[3];
    const float* Va     = (const float*)d_in[4];
    const float* Ba     = (const float*)d_in[5];
    float* out = (float*)d_out;

    was_kernel<<<128, 256>>>(prev, Wa, Ba);
    dim3 g2(NCHUNKS, M_TOTAL / BM);   // (8, 256)
    attn_gemm_kernel<<<g2, 256>>>(inputs, Ua, Va);
    softmax_kernel<<<BATCH, TSTEPS>>>();
    context_kernel<<<dim3(BATCH, DIM / 64), 256>>>(inputs, out);
}